// round 4
// baseline (speedup 1.0000x reference)
#include <cuda_runtime.h>
#include <cstdint>

#define B_ 64
#define T_ 1024
#define F_ 128
#define U_ 256

// Scratch for the input projection h = inputs @ R, layout [B, T, U].
__device__ float g_h[(size_t)B_ * T_ * U_];

// ---------------- helpers ----------------

__device__ __forceinline__ unsigned smem_u32(const void* p) {
    return (unsigned)__cvta_generic_to_shared(p);
}
// pack {s, s} into a 64-bit f32x2 operand
__device__ __forceinline__ unsigned long long dup2(float s) {
    unsigned long long r;
    asm("mov.b64 %0, {%1, %1};" : "=l"(r) : "r"(__float_as_uint(s)));
    return r;
}
__device__ __forceinline__ unsigned long long ffma2(unsigned long long a, unsigned long long b,
                                                    unsigned long long c) {
    unsigned long long d;
    asm("fma.rn.f32x2 %0, %1, %2, %3;" : "=l"(d) : "l"(a), "l"(b), "l"(c));
    return d;
}
__device__ __forceinline__ unsigned long long fadd2(unsigned long long a, unsigned long long b) {
    unsigned long long d;
    asm("add.rn.f32x2 %0, %1, %2;" : "=l"(d) : "l"(a), "l"(b));
    return d;
}
__device__ __forceinline__ float2 unpk(unsigned long long v) {
    unsigned lo, hi;
    asm("mov.b64 {%0, %1}, %2;" : "=r"(lo), "=r"(hi) : "l"(v));
    return make_float2(__uint_as_float(lo), __uint_as_float(hi));
}
__device__ __forceinline__ unsigned mapa_u32(unsigned addr, unsigned rank) {
    unsigned r;
    asm("mapa.shared::cluster.u32 %0, %1, %2;" : "=r"(r) : "r"(addr), "r"(rank));
    return r;
}
__device__ __forceinline__ void mbar_init(unsigned addr, unsigned cnt) {
    asm volatile("mbarrier.init.shared.b64 [%0], %1;" :: "r"(addr), "r"(cnt) : "memory");
}
__device__ __forceinline__ void st_remote_u64(unsigned addr, unsigned long long v) {
    asm volatile("st.shared::cluster.u64 [%0], %1;" :: "r"(addr), "l"(v) : "memory");
}
__device__ __forceinline__ void mbar_arrive_remote(unsigned addr) {
    asm volatile("mbarrier.arrive.release.cluster.shared::cluster.b64 _, [%0];"
                 :: "r"(addr) : "memory");
}
__device__ __forceinline__ void mbar_wait(unsigned addr, unsigned parity) {
    asm volatile(
        "{\n\t"
        ".reg .pred P;\n"
        "WAIT%=:\n\t"
        "mbarrier.try_wait.parity.acquire.cluster.shared::cta.b64 P, [%0], %1, 0x989680;\n\t"
        "@!P bra WAIT%=;\n\t"
        "}"
        :: "r"(addr), "r"(parity) : "memory");
}
__device__ __forceinline__ void cluster_sync_() {
    asm volatile("barrier.cluster.arrive.aligned;" ::: "memory");
    asm volatile("barrier.cluster.wait.aligned;" ::: "memory");
}
// accurate-enough tanh: |err| ~1e-6 rel, overflow-free (uses exp2(-2|x|log2e))
__device__ __forceinline__ float fast_tanh(float x) {
    float ax = fabsf(x) * -2.885390081777927f;  // -2*log2(e)
    float e;
    asm("ex2.approx.f32 %0, %1;" : "=f"(e) : "f"(ax));
    float num = 1.0f - e;
    float den = 1.0f + e;
    float r;
    asm("rcp.approx.f32 %0, %1;" : "=f"(r) : "f"(den));
    return copysignf(num * r, x);
}

// ---------------- phase 1: h = inputs @ R ----------------
// 256 threads: up = u-pair (0..127), fh = f-half (0..1). Each thread keeps
// R[64*fh .. 64*fh+63][2up..2up+1] as 64 packed f32x2 registers. Tiles of 16
// rows (b,t); inputs staged duplicated+transposed in smem for broadcast LDS.128.
__global__ void __launch_bounds__(256, 1)
proj_kernel(const float* __restrict__ inp, const float* __restrict__ R)
{
    __shared__ __align__(16) unsigned long long in_dupT[128 * 18];  // [f][r] pad 18
    __shared__ __align__(16) unsigned long long partsm[128 * 17];   // pad 17

    const int tid = threadIdx.x;
    const int up = tid & 127;
    const int fh = tid >> 7;

    unsigned long long w[64];
    const unsigned long long* R64 = (const unsigned long long*)R;
#pragma unroll
    for (int j = 0; j < 64; j++)
        w[j] = R64[(64 * fh + j) * 128 + up];

    const int ntiles = (B_ * T_) / 16;
    for (int tile = blockIdx.x; tile < ntiles; tile += gridDim.x) {
        const int row0 = tile * 16;
        __syncthreads();  // protect smem reuse across tiles
#pragma unroll
        for (int e = 0; e < 8; e++) {
            int idx = e * 256 + tid;
            int r = idx >> 7, f = idx & 127;
            float v = inp[(size_t)(row0 + r) * F_ + f];
            in_dupT[f * 18 + r] = dup2(v);
        }
        __syncthreads();

        unsigned long long acc[16];
#pragma unroll
        for (int r = 0; r < 16; r++) acc[r] = 0ull;

#pragma unroll
        for (int j = 0; j < 64; j++) {
            const int f = 64 * fh + j;
            const ulonglong2* col = (const ulonglong2*)&in_dupT[f * 18];
#pragma unroll
            for (int rr = 0; rr < 8; rr++) {
                ulonglong2 v = col[rr];  // rows 2rr, 2rr+1 (broadcast)
                acc[2 * rr]     = ffma2(v.x, w[j], acc[2 * rr]);
                acc[2 * rr + 1] = ffma2(v.y, w[j], acc[2 * rr + 1]);
            }
        }
        if (fh) {
#pragma unroll
            for (int r = 0; r < 16; r++) partsm[up * 17 + r] = acc[r];
        }
        __syncthreads();
        if (!fh) {
#pragma unroll
            for (int r = 0; r < 16; r++) {
                unsigned long long tot = fadd2(acc[r], partsm[up * 17 + r]);
                float2 o = unpk(tot);
                *(float2*)&g_h[(size_t)(row0 + r) * U_ + 2 * up] = o;
            }
        }
    }
}

// ---------------- phase 2: the recurrence ----------------
// One 2-CTA cluster per batch element. CTA rank r holds W[128r:128r+128, :]
// in registers (packed f32x2 column pairs) and produces state slice
// u in [128r, 128r+128). Per step: local K-half partials for all 256 u,
// kk-combine in smem, cross-CTA partial exchange via DSMEM + mbarrier
// (double-buffered), then tanh epilogue updates the local duplicated state.
__global__ void __launch_bounds__(256, 1) __cluster_dims__(2, 1, 1)
rnn_kernel(const float* __restrict__ W, const float* __restrict__ bias,
           const float* __restrict__ x0, float* __restrict__ out)
{
    __shared__ __align__(16) unsigned long long sdup[128];      // dup'd local state
    __shared__ __align__(16) unsigned long long part1[128];     // kk=1 partials
    __shared__ __align__(16) unsigned long long recvbuf[2][64]; // peer partials
    __shared__ __align__(8)  unsigned long long mbar[2];

    const int tid = threadIdx.x;
    const int up = tid & 127;   // u-pair 0..127 (global)
    const int kk = tid >> 7;    // k sub-half within my 128-row slice
    unsigned rank;
    asm("mov.u32 %0, %%cluster_ctarank;" : "=r"(rank));
    const int b = blockIdx.x >> 1;
    const int kbase = 128 * (int)rank;

    // weights: W[kbase + 64*kk + j][2up .. 2up+1], j = 0..63
    unsigned long long w[64];
    const unsigned long long* W64 = (const unsigned long long*)W;
#pragma unroll
    for (int j = 0; j < 64; j++)
        w[j] = W64[(kbase + 64 * kk + j) * 128 + up];

    if (tid < 128) sdup[tid] = dup2(x0[kbase + tid]);
    if (tid == 0) {
        mbar_init(smem_u32(&mbar[0]), 64);
        mbar_init(smem_u32(&mbar[1]), 64);
    }
    __syncthreads();
    cluster_sync_();  // mbarriers visible cluster-wide before any remote arrive

    const bool lead = (kk == 0);
    const bool owner = lead && ((up >> 6) == (int)rank);  // my output pairs
    const int slot = up & 63;

    float b0 = 0.f, b1 = 0.f;
    if (owner) { b0 = bias[2 * up]; b1 = bias[2 * up + 1]; }

    unsigned r_recv0 = 0, r_recv1 = 0, r_bar0 = 0, r_bar1 = 0;
    if (lead && !owner) {
        unsigned peer = rank ^ 1u;
        r_recv0 = mapa_u32(smem_u32(&recvbuf[0][slot]), peer);
        r_recv1 = mapa_u32(smem_u32(&recvbuf[1][slot]), peer);
        r_bar0  = mapa_u32(smem_u32(&mbar[0]), peer);
        r_bar1  = mapa_u32(smem_u32(&mbar[1]), peer);
    }
    const unsigned l_bar0 = smem_u32(&mbar[0]);
    const unsigned l_bar1 = smem_u32(&mbar[1]);

    const size_t hbase = (size_t)b * T_ * U_ + 2 * up;
    const ulonglong2* sd = (const ulonglong2*)(sdup + 64 * kk);

    for (int t = 0; t < T_; t++) {
        float2 h2 = make_float2(0.f, 0.f);
        if (owner) h2 = *(const float2*)&g_h[hbase + (size_t)t * U_];  // prefetch

        unsigned long long a0 = 0ull, a1 = 0ull;
#pragma unroll
        for (int j = 0; j < 32; j++) {
            ulonglong2 v = sd[j];  // {dup(s_2j), dup(s_2j+1)} broadcast
            a0 = ffma2(v.x, w[2 * j], a0);
            a1 = ffma2(v.y, w[2 * j + 1], a1);
        }
        unsigned long long acc = fadd2(a0, a1);

        if (kk) part1[up] = acc;
        __syncthreads();  // also fences all sdup reads before epilogue writes
        if (lead) {
            unsigned long long tot = fadd2(acc, part1[up]);
            if (!owner) {
                // ship partials for the peer's u-range
                unsigned ra = (t & 1) ? r_recv1 : r_recv0;
                unsigned ba = (t & 1) ? r_bar1 : r_bar0;
                st_remote_u64(ra, tot);
                mbar_arrive_remote(ba);
            } else {
                mbar_wait((t & 1) ? l_bar1 : l_bar0, (t >> 1) & 1);
                unsigned long long pr = recvbuf[t & 1][slot];
                float2 tp = unpk(tot);
                float2 pp = unpk(pr);
                float y0 = tp.x + pp.x + h2.x + b0;
                float y1 = tp.y + pp.y + h2.y + b1;
                float s0 = fast_tanh(y0);
                float s1 = fast_tanh(y1);
                ulonglong2 sv;
                sv.x = dup2(s0);
                sv.y = dup2(s1);
                *(ulonglong2*)&sdup[2 * slot] = sv;  // k_local = 2*slot
                *(float2*)&out[((size_t)t * B_ + b) * U_ + 2 * up] = make_float2(s0, s1);
            }
        }
        __syncthreads();  // new state visible before next step's FMAs
    }
    cluster_sync_();  // keep cluster alive until all remote traffic lands
}

// ---------------- launch ----------------

extern "C" void kernel_launch(void* const* d_in, const int* in_sizes, int n_in,
                              void* d_out, int out_size)
{
    (void)in_sizes; (void)n_in; (void)out_size;
    const float* inputs = (const float*)d_in[0];  // [B,T,F]
    const float* R      = (const float*)d_in[1];  // [F,U]
    const float* W      = (const float*)d_in[2];  // [U,U]
    const float* bias   = (const float*)d_in[3];  // [U]
    const float* x0     = (const float*)d_in[4];  // [U]
    float* out = (float*)d_out;                   // [T,B,U]

    proj_kernel<<<304, 256>>>(inputs, R);
    rnn_kernel<<<2 * B_, 256>>>(W, bias, x0, out);
}

// round 5
// speedup vs baseline: 1.2759x; 1.2759x over previous
#include <cuda_runtime.h>
#include <cstdint>

#define B_ 64
#define T_ 1024
#define F_ 128
#define U_ 256

// Scratch for the input projection h = inputs @ R, layout [B, T, U] (row = b*T+t).
__device__ float g_h[(size_t)B_ * T_ * U_];

// ---------------- helpers ----------------

__device__ __forceinline__ unsigned smem_u32(const void* p) {
    return (unsigned)__cvta_generic_to_shared(p);
}
__device__ __forceinline__ unsigned long long dup2(float s) {
    unsigned long long r;
    asm("mov.b64 %0, {%1, %1};" : "=l"(r) : "r"(__float_as_uint(s)));
    return r;
}
__device__ __forceinline__ unsigned long long pk2(float lo, float hi) {
    unsigned long long r;
    asm("mov.b64 %0, {%1, %2};" : "=l"(r)
        : "r"(__float_as_uint(lo)), "r"(__float_as_uint(hi)));
    return r;
}
__device__ __forceinline__ unsigned long long ffma2(unsigned long long a, unsigned long long b,
                                                    unsigned long long c) {
    unsigned long long d;
    asm("fma.rn.f32x2 %0, %1, %2, %3;" : "=l"(d) : "l"(a), "l"(b), "l"(c));
    return d;
}
__device__ __forceinline__ unsigned long long fadd2(unsigned long long a, unsigned long long b) {
    unsigned long long d;
    asm("add.rn.f32x2 %0, %1, %2;" : "=l"(d) : "l"(a), "l"(b));
    return d;
}
__device__ __forceinline__ float2 unpk(unsigned long long v) {
    unsigned lo, hi;
    asm("mov.b64 {%0, %1}, %2;" : "=r"(lo), "=r"(hi) : "l"(v));
    return make_float2(__uint_as_float(lo), __uint_as_float(hi));
}
__device__ __forceinline__ unsigned mapa_u32(unsigned addr, unsigned rank) {
    unsigned r;
    asm("mapa.shared::cluster.u32 %0, %1, %2;" : "=r"(r) : "r"(addr), "r"(rank));
    return r;
}
__device__ __forceinline__ void mbar_init(unsigned addr, unsigned cnt) {
    asm volatile("mbarrier.init.shared.b64 [%0], %1;" :: "r"(addr), "r"(cnt) : "memory");
}
__device__ __forceinline__ void mbar_expect_tx(unsigned addr, unsigned bytes) {
    asm volatile("mbarrier.arrive.expect_tx.shared::cta.b64 _, [%0], %1;"
                 :: "r"(addr), "r"(bytes) : "memory");
}
__device__ __forceinline__ void mbar_wait(unsigned addr, unsigned parity) {
    asm volatile(
        "{\n\t"
        ".reg .pred P;\n"
        "WAIT%=:\n\t"
        "mbarrier.try_wait.parity.acquire.cluster.shared::cta.b64 P, [%0], %1, 0x989680;\n\t"
        "@!P bra WAIT%=;\n\t"
        "}"
        :: "r"(addr), "r"(parity) : "memory");
}
// one-shot 512B SMEM->peer-SMEM bulk copy, tx-completion on the peer's mbarrier
__device__ __forceinline__ void bulk_copy_s2s(unsigned dst_cluster, unsigned src_cta,
                                              unsigned bytes, unsigned rbar_cluster) {
    asm volatile(
        "cp.async.bulk.shared::cluster.shared::cta.mbarrier::complete_tx::bytes "
        "[%0], [%1], %2, [%3];"
        :: "r"(dst_cluster), "r"(src_cta), "r"(bytes), "r"(rbar_cluster) : "memory");
}
__device__ __forceinline__ void cluster_sync_() {
    asm volatile("barrier.cluster.arrive.aligned;" ::: "memory");
    asm volatile("barrier.cluster.wait.aligned;" ::: "memory");
}
// accurate tanh: |err| ~1e-6 rel, overflow-free
__device__ __forceinline__ float fast_tanh(float x) {
    float ax = fabsf(x) * -2.885390081777927f;  // -2*log2(e)
    float e;
    asm("ex2.approx.f32 %0, %1;" : "=f"(e) : "f"(ax));
    float num = 1.0f - e;
    float den = 1.0f + e;
    float r;
    asm("rcp.approx.f32 %0, %1;" : "=f"(r) : "f"(den));
    return copysignf(num * r, x);
}

// ---------------- phase 1: h = inputs @ R ----------------
__global__ void __launch_bounds__(256, 1)
proj_kernel(const float* __restrict__ inp, const float* __restrict__ R)
{
    __shared__ __align__(16) unsigned long long in_dupT[128 * 18];  // [f][r] pad 18
    __shared__ __align__(16) unsigned long long partsm[128 * 17];   // pad 17

    const int tid = threadIdx.x;
    const int up = tid & 127;
    const int fh = tid >> 7;

    unsigned long long w[64];
    const unsigned long long* R64 = (const unsigned long long*)R;
#pragma unroll
    for (int j = 0; j < 64; j++)
        w[j] = R64[(64 * fh + j) * 128 + up];

    const int ntiles = (B_ * T_) / 16;
    for (int tile = blockIdx.x; tile < ntiles; tile += gridDim.x) {
        const int row0 = tile * 16;
        __syncthreads();
#pragma unroll
        for (int e = 0; e < 8; e++) {
            int idx = e * 256 + tid;
            int r = idx >> 7, f = idx & 127;
            float v = inp[(size_t)(row0 + r) * F_ + f];
            in_dupT[f * 18 + r] = dup2(v);
        }
        __syncthreads();

        unsigned long long acc[16];
#pragma unroll
        for (int r = 0; r < 16; r++) acc[r] = 0ull;

#pragma unroll
        for (int j = 0; j < 64; j++) {
            const int f = 64 * fh + j;
            const ulonglong2* col = (const ulonglong2*)&in_dupT[f * 18];
#pragma unroll
            for (int rr = 0; rr < 8; rr++) {
                ulonglong2 v = col[rr];
                acc[2 * rr]     = ffma2(v.x, w[j], acc[2 * rr]);
                acc[2 * rr + 1] = ffma2(v.y, w[j], acc[2 * rr + 1]);
            }
        }
        if (fh) {
#pragma unroll
            for (int r = 0; r < 16; r++) partsm[up * 17 + r] = acc[r];
        }
        __syncthreads();
        if (!fh) {
#pragma unroll
            for (int r = 0; r < 16; r++) {
                unsigned long long tot = fadd2(acc[r], partsm[up * 17 + r]);
                float2 o = unpk(tot);
                *(float2*)&g_h[(size_t)(row0 + r) * U_ + 2 * up] = o;
            }
        }
    }
}

// ---------------- phase 2: the recurrence (U-split) ----------------
// 2-CTA cluster per batch. CTA rank r produces u in [128r, 128r+128) using the
// FULL K=256 state; weights W[:, u-slice] register-resident (k-paired f32x2).
// Per step: local-half FMAs (own state, already in smem) overlap the in-flight
// 512B bulk copy of the peer's state half; wait tx-mbarrier; peer-half FMAs;
// pair-shuffle reduce; tanh; STS + STG; ONE __syncthreads; elect thread issues
// the bulk copy of the fresh state half to the peer. Double-buffered; the
// step handshake itself provides buffer backpressure.
__global__ void __launch_bounds__(256, 1) __cluster_dims__(2, 1, 1)
rnn_kernel(const float* __restrict__ W, const float* __restrict__ bias,
           const float* __restrict__ x0, float* __restrict__ out)
{
    __shared__ __align__(16) float s_loc[2][128];   // own slice (copy source)
    __shared__ __align__(16) float s_peer[2][128];  // peer slice (copy dest)
    __shared__ __align__(8)  unsigned long long mbar[2];

    const int tid = threadIdx.x;
    const int u  = tid >> 1;   // local u index 0..127
    const int kh = tid & 1;    // k sub-half selector
    unsigned rank;
    asm("mov.u32 %0, %%cluster_ctarank;" : "=r"(rank));
    const int b = blockIdx.x >> 1;
    const int gu    = 128 * (int)rank + u;
    const int lbase = 128 * (int)rank;          // k-range this CTA produces
    const int pbase = 128 * ((int)rank ^ 1);    // k-range the peer produces

    // weights: wl[m] = {W[lbase+64kh+2m][gu], W[lbase+64kh+2m+1][gu]}, m=0..31
    unsigned long long wl[32], wp[32];
#pragma unroll
    for (int m = 0; m < 32; m++) {
        int kl = lbase + 64 * kh + 2 * m;
        wl[m] = pk2(W[(size_t)kl * U_ + gu], W[(size_t)(kl + 1) * U_ + gu]);
        int kp = pbase + 64 * kh + 2 * m;
        wp[m] = pk2(W[(size_t)kp * U_ + gu], W[(size_t)(kp + 1) * U_ + gu]);
    }

    if (tid < 128) {
        s_loc[1][tid]  = x0[lbase + tid];
        s_peer[1][tid] = x0[pbase + tid];
    }
    if (tid == 0) {
        mbar_init(smem_u32(&mbar[0]), 1);
        mbar_init(smem_u32(&mbar[1]), 1);
    }
    __syncthreads();
    cluster_sync_();  // mbarriers + x0 visible cluster-wide before any copy

    const unsigned peer = rank ^ 1u;
    const unsigned l_src[2]  = { smem_u32(&s_loc[0][0]), smem_u32(&s_loc[1][0]) };
    const unsigned r_dst[2]  = { mapa_u32(smem_u32(&s_peer[0][0]), peer),
                                 mapa_u32(smem_u32(&s_peer[1][0]), peer) };
    const unsigned r_bar[2]  = { mapa_u32(smem_u32(&mbar[0]), peer),
                                 mapa_u32(smem_u32(&mbar[1]), peer) };
    const unsigned l_bar[2]  = { smem_u32(&mbar[0]), smem_u32(&mbar[1]) };

    const float bias_u = bias[gu];
    const float* hptr = &g_h[((size_t)b * T_) * U_ + gu];   // h[b][t][gu]
    float hcur = hptr[0];

    for (int t = 0; t < T_; t++) {
        const int prev = (t + 1) & 1;   // state_{t-1} buffer
        const int cur  = t & 1;         // state_t buffer

        // prefetch next h (clamped) — covers DRAM latency across the step
        int tn = (t + 1 < T_) ? (t + 1) : (T_ - 1);
        float hnext = hptr[(size_t)tn * U_];

        // post expected tx for this step's incoming peer state
        if (t > 0 && tid == 0) mbar_expect_tx(l_bar[prev], 512u);

        // ---- local-half FMAs (own state already in smem) ----
        unsigned long long a0 = 0ull, a1 = 0ull;
        const ulonglong2* sl = (const ulonglong2*)&s_loc[prev][64 * kh];
#pragma unroll
        for (int j = 0; j < 16; j++) {
            ulonglong2 v = sl[j];                 // {s[4j..4j+1]},{s[4j+2..4j+3]}
            a0 = ffma2(v.x, wl[2 * j],     a0);
            a1 = ffma2(v.y, wl[2 * j + 1], a1);
        }

        // ---- wait for the peer half (copy was issued at end of step t-1) ----
        if (t > 0) mbar_wait(l_bar[prev], ((t - 1) >> 1) & 1);

        const ulonglong2* sp = (const ulonglong2*)&s_peer[prev][64 * kh];
#pragma unroll
        for (int j = 0; j < 16; j++) {
            ulonglong2 v = sp[j];
            a0 = ffma2(v.x, wp[2 * j],     a0);
            a1 = ffma2(v.y, wp[2 * j + 1], a1);
        }

        // ---- reduce the 2 kh-partials: in-register + 1 butterfly shuffle ----
        float2 aa = unpk(fadd2(a0, a1));
        float s = aa.x + aa.y;
        s += __shfl_xor_sync(0xffffffffu, s, 1);

        float st = fast_tanh(s + hcur + bias_u);
        if (kh == 0) {
            s_loc[cur][u] = st;
            out[((size_t)t * B_ + b) * U_ + gu] = st;
        }
        hcur = hnext;

        __syncthreads();  // state_t visible CTA-wide (readers + async-proxy src)

        // ---- ship fresh state half to the peer: ONE 512B bulk copy ----
        if (tid == 0 && t < T_ - 1) {
            asm volatile("fence.proxy.async.shared::cta;" ::: "memory");
            bulk_copy_s2s(r_dst[cur], l_src[cur], 512u, r_bar[cur]);
        }
    }
    cluster_sync_();  // keep both CTAs alive until all cluster traffic lands
}

// ---------------- launch ----------------

extern "C" void kernel_launch(void* const* d_in, const int* in_sizes, int n_in,
                              void* d_out, int out_size)
{
    (void)in_sizes; (void)n_in; (void)out_size;
    const float* inputs = (const float*)d_in[0];  // [B,T,F]
    const float* R      = (const float*)d_in[1];  // [F,U]
    const float* W      = (const float*)d_in[2];  // [U,U]
    const float* bias   = (const float*)d_in[3];  // [U]
    const float* x0     = (const float*)d_in[4];  // [U]
    float* out = (float*)d_out;                   // [T,B,U]

    proj_kernel<<<304, 256>>>(inputs, R);
    rnn_kernel<<<2 * B_, 256>>>(W, bias, x0, out);
}